// round 2
// baseline (speedup 1.0000x reference)
#include <cuda_runtime.h>
#include <cuda_bf16.h>
#include <math.h>

// Model dims
#define NL 32
#define D  256
#define DI 512
#define NS 16      // d_state
#define RR 16      // dt_rank
#define KC 4       // d_conv
#define VV 4096
#define FF 1024
#define BB 32
#define LL 256
#define TT (BB*LL)   // 8192 tokens

// ---------------- scratch (static device globals; no allocation allowed) ----
__device__ float g_x  [TT * D];        // residual stream
__device__ float g_h  [TT * D];        // LN output
__device__ float g_xz [TT * 2 * DI];   // in_proj output
__device__ float g_xc [TT * DI];       // conv+silu output
__device__ float g_dbc[TT * 48];       // x_proj output (R + 2N = 48)
__device__ float g_dt [TT * DI];       // softplus dt
__device__ float g_y  [TT * DI];       // scan output (gated)
__device__ float g_h1 [TT * FF];       // MLP hidden

// ---------------- embedding --------------------------------------------------
__global__ void embed_kernel(const int* __restrict__ tok,
                             const float* __restrict__ emb,
                             float* __restrict__ x)
{
    int t = blockIdx.x, d = threadIdx.x;
    x[t * D + d] = emb[(size_t)tok[t] * D + d];
}

// ---------------- layernorm --------------------------------------------------
__global__ void ln_kernel(const float* __restrict__ x,
                          const float* __restrict__ w,
                          const float* __restrict__ b,
                          float* __restrict__ h)
{
    int t = blockIdx.x, d = threadIdx.x;
    float v = x[t * D + d];
    float s = v, s2 = v * v;
    #pragma unroll
    for (int o = 16; o > 0; o >>= 1) {
        s  += __shfl_xor_sync(0xffffffffu, s,  o);
        s2 += __shfl_xor_sync(0xffffffffu, s2, o);
    }
    __shared__ float ws[8], ws2[8];
    int wi = d >> 5;
    if ((d & 31) == 0) { ws[wi] = s; ws2[wi] = s2; }
    __syncthreads();
    if (d < 32) {
        float a  = (d < 8) ? ws[d]  : 0.f;
        float a2 = (d < 8) ? ws2[d] : 0.f;
        #pragma unroll
        for (int o = 4; o > 0; o >>= 1) {
            a  += __shfl_xor_sync(0xffffffffu, a,  o);
            a2 += __shfl_xor_sync(0xffffffffu, a2, o);
        }
        if (d == 0) { ws[0] = a; ws2[0] = a2; }
    }
    __syncthreads();
    float mu  = ws[0] * (1.f / D);
    float var = ws2[0] * (1.f / D) - mu * mu;
    float inv = rsqrtf(var + 1e-5f);
    h[t * D + d] = (v - mu) * inv * w[d] + b[d];
}

// ---------------- TF32 tensor-core NT GEMM ----------------------------------
// C[m][n] = dot(A[m,:], B[n,:]) + epilogue
// A: M x K (lda), B: N x K (ldb), C: M x ldc
// EPI: 0 plain, 1 bias+relu, 2 bias, 3 residual add, 4 bias+softplus
#define BM 128
#define BN 64
#define BKK 16
#define SPAD 20          // smem row stride (floats): conflict-free & 16B-aligned

__device__ __forceinline__ float to_tf32(float x) {
    asm("cvt.rna.tf32.f32 %0, %1;" : "=f"(x) : "f"(x));
    return x;
}

__device__ __forceinline__ void mma_tf32(float c[4],
                                         float a0, float a1, float a2, float a3,
                                         float b0, float b1)
{
    unsigned ua0 = __float_as_uint(a0), ua1 = __float_as_uint(a1);
    unsigned ua2 = __float_as_uint(a2), ua3 = __float_as_uint(a3);
    unsigned ub0 = __float_as_uint(b0), ub1 = __float_as_uint(b1);
    asm volatile(
        "mma.sync.aligned.m16n8k8.row.col.f32.tf32.tf32.f32 "
        "{%0,%1,%2,%3}, {%4,%5,%6,%7}, {%8,%9}, {%0,%1,%2,%3};"
        : "+f"(c[0]), "+f"(c[1]), "+f"(c[2]), "+f"(c[3])
        : "r"(ua0), "r"(ua1), "r"(ua2), "r"(ua3), "r"(ub0), "r"(ub1));
}

template<int EPI>
__global__ __launch_bounds__(256)
void gemm_tc(const float* __restrict__ A, int lda,
             const float* __restrict__ B, int ldb,
             float* __restrict__ C, int ldc,
             const float* __restrict__ bias,
             const float* __restrict__ res,
             int M, int N, int K)
{
    __shared__ float As[2][BM][SPAD];
    __shared__ float Bs[2][BN][SPAD];

    int tid  = threadIdx.x;
    int bm   = blockIdx.y * BM, bn = blockIdx.x * BN;
    int warp = tid >> 5, lane = tid & 31;
    int wm = warp & 3, wn = warp >> 2;       // 4 x 2 warp grid
    int grp = lane >> 2, tig = lane & 3;     // mma fragment coords

    // global-load addressing
    int ar  = tid >> 2, ac4 = tid & 3;       // A: rows ar, ar+64 ; k-chunk ac4
    int br  = tid >> 2, bc4 = tid & 3;       // B: row br        ; k-chunk bc4
    bool bok = (bn + br < N);

    float acc[2][4][4];
    #pragma unroll
    for (int mt = 0; mt < 2; mt++)
        #pragma unroll
        for (int nt = 0; nt < 4; nt++)
            #pragma unroll
            for (int i = 0; i < 4; i++) acc[mt][nt][i] = 0.f;

    // ---- prologue: load tile k0=0 into stage 0
    float4 ra0, ra1, rb;
    {
        ra0 = *reinterpret_cast<const float4*>(A + (size_t)(bm + ar)      * lda + ac4 * 4);
        ra1 = *reinterpret_cast<const float4*>(A + (size_t)(bm + ar + 64) * lda + ac4 * 4);
        rb  = make_float4(0.f, 0.f, 0.f, 0.f);
        if (bok)
            rb = *reinterpret_cast<const float4*>(B + (size_t)(bn + br) * ldb + bc4 * 4);
        float4 t0 = make_float4(to_tf32(ra0.x), to_tf32(ra0.y), to_tf32(ra0.z), to_tf32(ra0.w));
        float4 t1 = make_float4(to_tf32(ra1.x), to_tf32(ra1.y), to_tf32(ra1.z), to_tf32(ra1.w));
        float4 tb = make_float4(to_tf32(rb.x),  to_tf32(rb.y),  to_tf32(rb.z),  to_tf32(rb.w));
        *reinterpret_cast<float4*>(&As[0][ar][ac4 * 4])      = t0;
        *reinterpret_cast<float4*>(&As[0][ar + 64][ac4 * 4]) = t1;
        *reinterpret_cast<float4*>(&Bs[0][br][bc4 * 4])      = tb;
    }
    __syncthreads();

    int s = 0;
    for (int k0 = 0; k0 < K; k0 += BKK, s ^= 1) {
        bool more = (k0 + BKK < K);
        if (more) {
            ra0 = *reinterpret_cast<const float4*>(A + (size_t)(bm + ar)      * lda + k0 + BKK + ac4 * 4);
            ra1 = *reinterpret_cast<const float4*>(A + (size_t)(bm + ar + 64) * lda + k0 + BKK + ac4 * 4);
            rb  = make_float4(0.f, 0.f, 0.f, 0.f);
            if (bok)
                rb = *reinterpret_cast<const float4*>(B + (size_t)(bn + br) * ldb + k0 + BKK + bc4 * 4);
        }

        // compute on stage s
        #pragma unroll
        for (int ks = 0; ks < BKK; ks += 8) {
            float a[2][4];
            #pragma unroll
            for (int mt = 0; mt < 2; mt++) {
                int r = wm * 32 + mt * 16 + grp;
                a[mt][0] = As[s][r][ks + tig];
                a[mt][1] = As[s][r + 8][ks + tig];
                a[mt][2] = As[s][r][ks + tig + 4];
                a[mt][3] = As[s][r + 8][ks + tig + 4];
            }
            float b[4][2];
            #pragma unroll
            for (int nt = 0; nt < 4; nt++) {
                int c = wn * 32 + nt * 8 + grp;
                b[nt][0] = Bs[s][c][ks + tig];
                b[nt][1] = Bs[s][c][ks + tig + 4];
            }
            #pragma unroll
            for (int mt = 0; mt < 2; mt++)
                #pragma unroll
                for (int nt = 0; nt < 4; nt++)
                    mma_tf32(acc[mt][nt], a[mt][0], a[mt][1], a[mt][2], a[mt][3],
                             b[nt][0], b[nt][1]);
        }

        if (more) {
            float4 t0 = make_float4(to_tf32(ra0.x), to_tf32(ra0.y), to_tf32(ra0.z), to_tf32(ra0.w));
            float4 t1 = make_float4(to_tf32(ra1.x), to_tf32(ra1.y), to_tf32(ra1.z), to_tf32(ra1.w));
            float4 tb = make_float4(to_tf32(rb.x),  to_tf32(rb.y),  to_tf32(rb.z),  to_tf32(rb.w));
            *reinterpret_cast<float4*>(&As[s ^ 1][ar][ac4 * 4])      = t0;
            *reinterpret_cast<float4*>(&As[s ^ 1][ar + 64][ac4 * 4]) = t1;
            *reinterpret_cast<float4*>(&Bs[s ^ 1][br][bc4 * 4])      = tb;
        }
        __syncthreads();
    }

    // ---- epilogue
    #pragma unroll
    for (int mt = 0; mt < 2; mt++) {
        int r0 = bm + wm * 32 + mt * 16 + grp;
        #pragma unroll
        for (int nt = 0; nt < 4; nt++) {
            int col = bn + wn * 32 + nt * 8 + tig * 2;
            if (col >= N) continue;
            float v[4];
            #pragma unroll
            for (int i = 0; i < 4; i++) v[i] = acc[mt][nt][i];
            if (EPI == 1 || EPI == 2 || EPI == 4) {
                float b0 = bias[col], b1 = bias[col + 1];
                v[0] += b0; v[1] += b1; v[2] += b0; v[3] += b1;
                if (EPI == 1) {
                    #pragma unroll
                    for (int i = 0; i < 4; i++) v[i] = fmaxf(v[i], 0.f);
                } else if (EPI == 4) {
                    #pragma unroll
                    for (int i = 0; i < 4; i++)
                        v[i] = (v[i] > 20.f) ? v[i] : log1pf(expf(v[i]));
                }
            }
            size_t o0 = (size_t)r0 * ldc + col;
            size_t o1 = (size_t)(r0 + 8) * ldc + col;
            if (EPI == 3) {
                float2 r0v = *reinterpret_cast<const float2*>(res + o0);
                float2 r1v = *reinterpret_cast<const float2*>(res + o1);
                v[0] += r0v.x; v[1] += r0v.y; v[2] += r1v.x; v[3] += r1v.y;
            }
            *reinterpret_cast<float2*>(C + o0) = make_float2(v[0], v[1]);
            *reinterpret_cast<float2*>(C + o1) = make_float2(v[2], v[3]);
        }
    }
}

// ---------------- causal depthwise conv1d + SiLU ----------------------------
__global__ void conv_kernel(const float* __restrict__ xz,
                            const float* __restrict__ cw,
                            const float* __restrict__ cb,
                            float* __restrict__ xc)
{
    int t = blockIdx.x;
    int e = blockIdx.y * 256 + threadIdx.x;
    int l = t & (LL - 1);
    float acc = cb[e];
    #pragma unroll
    for (int k = 0; k < KC; k++) {
        int ll = l - (KC - 1) + k;
        if (ll >= 0)
            acc = fmaf(xz[(size_t)(t - (KC - 1) + k) * (2 * DI) + e], cw[e * KC + k], acc);
    }
    float s = 1.f / (1.f + expf(-acc));
    xc[(size_t)t * DI + e] = acc * s;
}

// ---------------- selective scan + skip + gate ------------------------------
__global__ void scan_kernel(const float* __restrict__ dbc,
                            const float* __restrict__ dtf,
                            const float* __restrict__ xc,
                            const float* __restrict__ xz,
                            const float* __restrict__ A_log,
                            const float* __restrict__ Dskip,
                            float* __restrict__ y)
{
    int b = blockIdx.y;
    int tid = threadIdx.x;
    int e = blockIdx.x * 128 + tid;
    __shared__ float sB[2][NS], sC[2][NS];

    float A[NS], h[NS];
    #pragma unroll
    for (int n = 0; n < NS; n++) {
        A[n] = -expf(A_log[e * NS + n]);
        h[n] = 0.f;
    }
    float Ds = Dskip[e];

    {
        int t0 = b * LL;
        if (tid < NS)            sB[0][tid]      = dbc[(size_t)t0 * 48 + RR + tid];
        else if (tid < 2 * NS)   sC[0][tid - NS] = dbc[(size_t)t0 * 48 + RR + NS + (tid - NS)];
    }
    __syncthreads();

    for (int l = 0; l < LL; l++) {
        int p = l & 1;
        if (l + 1 < LL) {
            int t1 = b * LL + l + 1;
            if (tid < NS)          sB[p ^ 1][tid]      = dbc[(size_t)t1 * 48 + RR + tid];
            else if (tid < 2 * NS) sC[p ^ 1][tid - NS] = dbc[(size_t)t1 * 48 + RR + NS + (tid - NS)];
        }
        int t = b * LL + l;
        float dtv = dtf[(size_t)t * DI + e];
        float xv  = xc[(size_t)t * DI + e];
        float du  = dtv * xv;
        float acc = 0.f;
        #pragma unroll
        for (int n = 0; n < NS; n++) {
            float dA = expf(dtv * A[n]);
            h[n] = fmaf(h[n], dA, du * sB[p][n]);
            acc = fmaf(h[n], sC[p][n], acc);
        }
        float zv = xz[(size_t)t * (2 * DI) + DI + e];
        float sig = 1.f / (1.f + expf(-zv));
        y[(size_t)t * DI + e] = (acc + xv * Ds) * (zv * sig);
        __syncthreads();
    }
}

// ---------------- host side --------------------------------------------------
extern "C" void kernel_launch(void* const* d_in, const int* in_sizes, int n_in,
                              void* d_out, int out_size)
{
    const int*   tok    = (const int*)  d_in[0];
    const float* emb    = (const float*)d_in[1];
    const float* ln_w   = (const float*)d_in[2];
    const float* ln_b   = (const float*)d_in[3];
    const float* in_w   = (const float*)d_in[4];   // (NL, 2DI, D)
    const float* conv_w = (const float*)d_in[5];   // (NL, DI, K)
    const float* conv_b = (const float*)d_in[6];   // (NL, DI)
    const float* xp_w   = (const float*)d_in[7];   // (NL, 48, DI)
    const float* dt_w   = (const float*)d_in[8];   // (NL, DI, R)
    const float* dt_b   = (const float*)d_in[9];   // (NL, DI)
    const float* A_log  = (const float*)d_in[10];  // (NL, DI, N)
    const float* Dskip  = (const float*)d_in[11];  // (NL, DI)
    const float* out_w  = (const float*)d_in[12];  // (NL, D, DI)
    const float* W1     = (const float*)d_in[13];  // (FF, D)
    const float* b1     = (const float*)d_in[14];
    const float* W2     = (const float*)d_in[15];  // (V, FF)
    const float* b2     = (const float*)d_in[16];
    float* out = (float*)d_out;

    float *px, *ph, *pxz, *pxc, *pdbc, *pdt, *py, *ph1;
    cudaGetSymbolAddress((void**)&px,   g_x);
    cudaGetSymbolAddress((void**)&ph,   g_h);
    cudaGetSymbolAddress((void**)&pxz,  g_xz);
    cudaGetSymbolAddress((void**)&pxc,  g_xc);
    cudaGetSymbolAddress((void**)&pdbc, g_dbc);
    cudaGetSymbolAddress((void**)&pdt,  g_dt);
    cudaGetSymbolAddress((void**)&py,   g_y);
    cudaGetSymbolAddress((void**)&ph1,  g_h1);

    embed_kernel<<<TT, D>>>(tok, emb, px);

    for (int l = 0; l < NL; l++) {
        const float* lw  = ln_w   + (size_t)l * D;
        const float* lb  = ln_b   + (size_t)l * D;
        const float* iw  = in_w   + (size_t)l * 2 * DI * D;
        const float* cw  = conv_w + (size_t)l * DI * KC;
        const float* cb  = conv_b + (size_t)l * DI;
        const float* xw  = xp_w   + (size_t)l * 48 * DI;
        const float* dw  = dt_w   + (size_t)l * DI * RR;
        const float* db  = dt_b   + (size_t)l * DI;
        const float* al  = A_log  + (size_t)l * DI * NS;
        const float* ds  = Dskip  + (size_t)l * DI;
        const float* ow  = out_w  + (size_t)l * D * DI;

        ln_kernel<<<TT, D>>>(px, lw, lb, ph);

        // xz = LN(x) @ in_w^T   (8192 x 1024 x 256)
        gemm_tc<0><<<dim3((2 * DI) / BN, TT / BM), 256>>>(
            ph, D, iw, D, pxz, 2 * DI, nullptr, nullptr, TT, 2 * DI, D);

        // conv + silu -> xc
        conv_kernel<<<dim3(TT, 2), 256>>>(pxz, cw, cb, pxc);

        // dbc = xc @ xp_w^T   (8192 x 48 x 512)
        gemm_tc<0><<<dim3(1, TT / BM), 256>>>(
            pxc, DI, xw, DI, pdbc, 48, nullptr, nullptr, TT, 48, DI);

        // dt = softplus(dbc[:, :16] @ dt_w^T + dt_b)   (8192 x 512 x 16)
        gemm_tc<4><<<dim3(DI / BN, TT / BM), 256>>>(
            pdbc, 48, dw, RR, pdt, DI, db, nullptr, TT, DI, RR);

        // selective scan + D-skip + SiLU(z) gate
        scan_kernel<<<dim3(4, BB), 128>>>(pdbc, pdt, pxc, pxz, al, ds, py);

        // x += y @ out_w^T   (8192 x 256 x 512), residual fused
        gemm_tc<3><<<dim3(D / BN, TT / BM), 256>>>(
            py, DI, ow, DI, px, D, nullptr, px, TT, D, DI);
    }

    // head: h1 = relu(x @ W1^T + b1)
    gemm_tc<1><<<dim3(FF / BN, TT / BM), 256>>>(
        px, D, W1, D, ph1, FF, b1, nullptr, TT, FF, D);
    // logits = h1 @ W2^T + b2
    gemm_tc<2><<<dim3(VV / BN, TT / BM), 256>>>(
        ph1, FF, W2, FF, out, VV, b2, nullptr, TT, VV, FF);
}

// round 4
// speedup vs baseline: 1.4840x; 1.4840x over previous
#include <cuda_runtime.h>
#include <cuda_bf16.h>
#include <math.h>
#include <cstdint>

// Model dims
#define NL 32
#define D  256
#define DI 512
#define NS 16
#define RR 16
#define KC 4
#define VV 4096
#define FF 1024
#define BB 32
#define LL 256
#define TT (BB*LL)

// ---------------- scratch ----------------------------------------------------
__device__ float g_x  [TT * D];
__device__ float g_h  [TT * D];
__device__ float g_xz [TT * 2 * DI];
__device__ float g_xc [TT * DI];
__device__ float g_dbc[TT * 48];
__device__ float g_dt [TT * DI];
__device__ float g_y  [TT * DI];
__device__ float g_h1 [TT * FF];

// ---------------- packed f32x2 helpers ---------------------------------------
#define PACK_AA(dst, x) \
    asm("mov.b64 %0, {%1, %1};" : "=l"(dst) : "r"(__float_as_uint(x)))
#define FMA2(acc, a, b) \
    asm("fma.rn.f32x2 %0, %1, %2, %0;" : "+l"(acc) : "l"(a), "l"(b))
#define UNPACK2(lo, hi, v) \
    asm("mov.b64 {%0, %1}, %2;" : "=r"(lo), "=r"(hi) : "l"(v))

// ---------------- FFMA2 NT GEMM ----------------------------------------------
// C[m][n] = dot(A[m,:], B[n,:]) + epilogue
// A: M x K (lda), B: N x K (ldb), C: M x ldc. M multiple of 128, N mult of 8,
// K multiple of 16.
// EPI: 0 plain, 1 bias+relu, 2 bias, 3 residual add, 4 bias+softplus
#define BM 128
#define BN 128
#define BK 16
#define SROW 132   // padded smem row stride (floats)

template<int EPI>
__global__ __launch_bounds__(256)
void gemm_ffma2(const float* __restrict__ A, int lda,
                const float* __restrict__ B, int ldb,
                float* __restrict__ C, int ldc,
                const float* __restrict__ bias,
                const float* __restrict__ res,
                int N, int K)
{
    __shared__ float As[2][BK][SROW];   // k-major
    __shared__ float Bs[2][BK][SROW];   // k-major

    int tid = threadIdx.x;
    int bm = blockIdx.y * BM, bn = blockIdx.x * BN;
    int tx = tid & 15, ty = tid >> 4;
    int m0 = ty * 8, n0 = tx * 8;

    // global load mapping: (row = tid>>2 [+64], kcol = (tid&3)*4), 2 halves
    int lr = tid >> 2;
    int lk = (tid & 3) * 4;

    unsigned long long acc[8][4];
    #pragma unroll
    for (int i = 0; i < 8; i++)
        #pragma unroll
        for (int j = 0; j < 4; j++) acc[i][j] = 0ull;

    float4 pa[2], pb[2];

    // fetch chunk k0 into registers
    auto fetch = [&](int k0) {
        #pragma unroll
        for (int h = 0; h < 2; h++) {
            int r = lr + h * 64;
            pa[h] = *reinterpret_cast<const float4*>(
                A + (size_t)(bm + r) * lda + k0 + lk);
            pb[h] = make_float4(0.f, 0.f, 0.f, 0.f);
            if (bn + r < N)
                pb[h] = *reinterpret_cast<const float4*>(
                    B + (size_t)(bn + r) * ldb + k0 + lk);
        }
    };
    // store registers into smem buffer (transposed to k-major)
    auto stage = [&](int buf) {
        #pragma unroll
        for (int h = 0; h < 2; h++) {
            int r = lr + h * 64;
            As[buf][lk + 0][r] = pa[h].x;
            As[buf][lk + 1][r] = pa[h].y;
            As[buf][lk + 2][r] = pa[h].z;
            As[buf][lk + 3][r] = pa[h].w;
            Bs[buf][lk + 0][r] = pb[h].x;
            Bs[buf][lk + 1][r] = pb[h].y;
            Bs[buf][lk + 2][r] = pb[h].z;
            Bs[buf][lk + 3][r] = pb[h].w;
        }
    };

    int NC = K / BK;
    fetch(0);
    stage(0);
    __syncthreads();

    for (int kc = 0; kc < NC; kc++) {
        int buf = kc & 1;
        if (kc + 1 < NC) fetch((kc + 1) * BK);

        #pragma unroll
        for (int k = 0; k < BK; k++) {
            float4 a0 = *reinterpret_cast<const float4*>(&As[buf][k][m0]);
            float4 a1 = *reinterpret_cast<const float4*>(&As[buf][k][m0 + 4]);
            ulonglong2 b0 = *reinterpret_cast<const ulonglong2*>(&Bs[buf][k][n0]);
            ulonglong2 b1 = *reinterpret_cast<const ulonglong2*>(&Bs[buf][k][n0 + 4]);
            float av[8] = {a0.x, a0.y, a0.z, a0.w, a1.x, a1.y, a1.z, a1.w};
            unsigned long long bb[4] = {b0.x, b0.y, b1.x, b1.y};
            #pragma unroll
            for (int i = 0; i < 8; i++) {
                unsigned long long aa;
                PACK_AA(aa, av[i]);
                #pragma unroll
                for (int j = 0; j < 4; j++)
                    FMA2(acc[i][j], aa, bb[j]);
            }
        }

        if (kc + 1 < NC) {
            stage(buf ^ 1);
            __syncthreads();
        }
    }

    // ---- epilogue
    if (bn + n0 >= N) return;   // all N are multiples of 8; whole group in/out
    #pragma unroll
    for (int i = 0; i < 8; i++) {
        int row = bm + m0 + i;
        float v[8];
        #pragma unroll
        for (int j = 0; j < 4; j++) {
            unsigned lo, hi;
            UNPACK2(lo, hi, acc[i][j]);
            v[2 * j]     = __uint_as_float(lo);
            v[2 * j + 1] = __uint_as_float(hi);
        }
        if (EPI == 1 || EPI == 2 || EPI == 4) {
            #pragma unroll
            for (int j = 0; j < 8; j++) v[j] += bias[bn + n0 + j];
            if (EPI == 1) {
                #pragma unroll
                for (int j = 0; j < 8; j++) v[j] = fmaxf(v[j], 0.f);
            } else if (EPI == 4) {
                #pragma unroll
                for (int j = 0; j < 8; j++)
                    v[j] = (v[j] > 20.f) ? v[j] : log1pf(expf(v[j]));
            }
        }
        size_t o = (size_t)row * ldc + bn + n0;
        if (EPI == 3) {
            float4 r0 = *reinterpret_cast<const float4*>(res + o);
            float4 r1 = *reinterpret_cast<const float4*>(res + o + 4);
            v[0] += r0.x; v[1] += r0.y; v[2] += r0.z; v[3] += r0.w;
            v[4] += r1.x; v[5] += r1.y; v[6] += r1.z; v[7] += r1.w;
        }
        *reinterpret_cast<float4*>(C + o)     = make_float4(v[0], v[1], v[2], v[3]);
        *reinterpret_cast<float4*>(C + o + 4) = make_float4(v[4], v[5], v[6], v[7]);
    }
}

// ---------------- embedding --------------------------------------------------
__global__ void embed_kernel(const int* __restrict__ tok,
                             const float* __restrict__ emb,
                             float* __restrict__ x)
{
    int t = blockIdx.x, d = threadIdx.x;
    x[t * D + d] = emb[(size_t)tok[t] * D + d];
}

// ---------------- layernorm --------------------------------------------------
__global__ void ln_kernel(const float* __restrict__ x,
                          const float* __restrict__ w,
                          const float* __restrict__ b,
                          float* __restrict__ h)
{
    int t = blockIdx.x, d = threadIdx.x;
    float v = x[t * D + d];
    float s = v, s2 = v * v;
    #pragma unroll
    for (int o = 16; o > 0; o >>= 1) {
        s  += __shfl_xor_sync(0xffffffffu, s,  o);
        s2 += __shfl_xor_sync(0xffffffffu, s2, o);
    }
    __shared__ float ws[8], ws2[8];
    int wi = d >> 5;
    if ((d & 31) == 0) { ws[wi] = s; ws2[wi] = s2; }
    __syncthreads();
    if (d < 32) {
        float a  = (d < 8) ? ws[d]  : 0.f;
        float a2 = (d < 8) ? ws2[d] : 0.f;
        #pragma unroll
        for (int o = 4; o > 0; o >>= 1) {
            a  += __shfl_xor_sync(0xffffffffu, a,  o);
            a2 += __shfl_xor_sync(0xffffffffu, a2, o);
        }
        if (d == 0) { ws[0] = a; ws2[0] = a2; }
    }
    __syncthreads();
    float mu  = ws[0] * (1.f / D);
    float var = ws2[0] * (1.f / D) - mu * mu;
    float inv = rsqrtf(var + 1e-5f);
    h[t * D + d] = (v - mu) * inv * w[d] + b[d];
}

// ---------------- causal depthwise conv1d + SiLU ----------------------------
__global__ void conv_kernel(const float* __restrict__ xz,
                            const float* __restrict__ cw,
                            const float* __restrict__ cb,
                            float* __restrict__ xc)
{
    int t = blockIdx.x;
    int e = blockIdx.y * 256 + threadIdx.x;
    int l = t & (LL - 1);
    float acc = cb[e];
    #pragma unroll
    for (int k = 0; k < KC; k++) {
        int ll = l - (KC - 1) + k;
        if (ll >= 0)
            acc = fmaf(xz[(size_t)(t - (KC - 1) + k) * (2 * DI) + e], cw[e * KC + k], acc);
    }
    float s = 1.f / (1.f + __expf(-acc));
    xc[(size_t)t * DI + e] = acc * s;
}

// ---------------- selective scan + skip + gate ------------------------------
__global__ void scan_kernel(const float* __restrict__ dbc,
                            const float* __restrict__ dtf,
                            const float* __restrict__ xc,
                            const float* __restrict__ xz,
                            const float* __restrict__ A_log,
                            const float* __restrict__ Dskip,
                            float* __restrict__ y)
{
    int b = blockIdx.y;
    int tid = threadIdx.x;
    int e = blockIdx.x * 128 + tid;
    __shared__ float sB[8][NS], sC[8][NS];

    float A[NS], h[NS];
    #pragma unroll
    for (int n = 0; n < NS; n++) {
        A[n] = -__expf(A_log[e * NS + n]);
        h[n] = 0.f;
    }
    float Ds = Dskip[e];

    for (int g = 0; g < LL / 8; g++) {
        __syncthreads();
        #pragma unroll
        for (int i = 0; i < 2; i++) {
            int id = tid + i * 128;
            int st = id >> 5, j = id & 31;
            int t = b * LL + g * 8 + st;
            float v = dbc[(size_t)t * 48 + RR + j];
            if (j < NS) sB[st][j] = v;
            else        sC[st][j - NS] = v;
        }
        __syncthreads();
        #pragma unroll
        for (int s = 0; s < 8; s++) {
            int t = b * LL + g * 8 + s;
            float dtv = dtf[(size_t)t * DI + e];
            float xv  = xc[(size_t)t * DI + e];
            float du  = dtv * xv;
            float acc = 0.f;
            #pragma unroll
            for (int n = 0; n < NS; n++) {
                float dA = __expf(dtv * A[n]);
                h[n] = fmaf(h[n], dA, du * sB[s][n]);
                acc = fmaf(h[n], sC[s][n], acc);
            }
            float zv = xz[(size_t)t * (2 * DI) + DI + e];
            float sig = 1.f / (1.f + __expf(-zv));
            y[(size_t)t * DI + e] = (acc + xv * Ds) * (zv * sig);
        }
    }
}

// ---------------- host side --------------------------------------------------
extern "C" void kernel_launch(void* const* d_in, const int* in_sizes, int n_in,
                              void* d_out, int out_size)
{
    const int*   tok    = (const int*)  d_in[0];
    const float* emb    = (const float*)d_in[1];
    const float* ln_w   = (const float*)d_in[2];
    const float* ln_b   = (const float*)d_in[3];
    const float* in_w   = (const float*)d_in[4];
    const float* conv_w = (const float*)d_in[5];
    const float* conv_b = (const float*)d_in[6];
    const float* xp_w   = (const float*)d_in[7];
    const float* dt_w   = (const float*)d_in[8];
    const float* dt_b   = (const float*)d_in[9];
    const float* A_log  = (const float*)d_in[10];
    const float* Dskip  = (const float*)d_in[11];
    const float* out_w  = (const float*)d_in[12];
    const float* W1     = (const float*)d_in[13];
    const float* b1     = (const float*)d_in[14];
    const float* W2     = (const float*)d_in[15];
    const float* b2     = (const float*)d_in[16];
    float* out = (float*)d_out;

    float *px, *ph, *pxz, *pxc, *pdbc, *pdt, *py, *ph1;
    cudaGetSymbolAddress((void**)&px,   g_x);
    cudaGetSymbolAddress((void**)&ph,   g_h);
    cudaGetSymbolAddress((void**)&pxz,  g_xz);
    cudaGetSymbolAddress((void**)&pxc,  g_xc);
    cudaGetSymbolAddress((void**)&pdbc, g_dbc);
    cudaGetSymbolAddress((void**)&pdt,  g_dt);
    cudaGetSymbolAddress((void**)&py,   g_y);
    cudaGetSymbolAddress((void**)&ph1,  g_h1);

    embed_kernel<<<TT, D>>>(tok, emb, px);

    for (int l = 0; l < NL; l++) {
        const float* lw  = ln_w   + (size_t)l * D;
        const float* lb  = ln_b   + (size_t)l * D;
        const float* iw  = in_w   + (size_t)l * 2 * DI * D;
        const float* cw  = conv_w + (size_t)l * DI * KC;
        const float* cb  = conv_b + (size_t)l * DI;
        const float* xw  = xp_w   + (size_t)l * 48 * DI;
        const float* dw  = dt_w   + (size_t)l * DI * RR;
        const float* db  = dt_b   + (size_t)l * DI;
        const float* al  = A_log  + (size_t)l * DI * NS;
        const float* ds  = Dskip  + (size_t)l * DI;
        const float* ow  = out_w  + (size_t)l * D * DI;

        ln_kernel<<<TT, D>>>(px, lw, lb, ph);

        // xz = LN(x) @ in_w^T   (8192 x 1024 x 256)
        gemm_ffma2<0><<<dim3((2 * DI) / BN, TT / BM), 256>>>(
            ph, D, iw, D, pxz, 2 * DI, nullptr, nullptr, 2 * DI, D);

        conv_kernel<<<dim3(TT, 2), 256>>>(pxz, cw, cb, pxc);

        // dbc = xc @ xp_w^T   (8192 x 48 x 512)
        gemm_ffma2<0><<<dim3(1, TT / BM), 256>>>(
            pxc, DI, xw, DI, pdbc, 48, nullptr, nullptr, 48, DI);

        // dt = softplus(dbc[:, :16] @ dt_w^T + dt_b)   (8192 x 512 x 16)
        gemm_ffma2<4><<<dim3(DI / BN, TT / BM), 256>>>(
            pdbc, 48, dw, RR, pdt, DI, db, nullptr, DI, RR);

        scan_kernel<<<dim3(4, BB), 128>>>(pdbc, pdt, pxc, pxz, al, ds, py);

        // x += y @ out_w^T   (8192 x 256 x 512)
        gemm_ffma2<3><<<dim3(D / BN, TT / BM), 256>>>(
            py, DI, ow, DI, px, D, nullptr, px, D, DI);
    }

    // head
    gemm_ffma2<1><<<dim3(FF / BN, TT / BM), 256>>>(
        px, D, W1, D, ph1, FF, b1, nullptr, FF, D);
    gemm_ffma2<2><<<dim3(VV / BN, TT / BM), 256>>>(
        ph1, FF, W2, FF, out, VV, b2, nullptr, VV, FF);
}